// round 16
// baseline (speedup 1.0000x reference)
#include <cuda_runtime.h>
#include <cuda_fp16.h>
#include <cstdint>

// ---------------------------------------------------------------------------
// MotionGenerator seq2seq LSTM (B=512,H=512,L=2,T=120) — persistent kernel.
// Tensor-core cells via mma.sync fp16 (plain sm_103 target).
// R16: 256 CTAs (2/SM); chunk=128 K-cols (36.9KB, 8 chunks/cell instead of
// 16) -> half the sync/wait fixed costs; 3-stage ring (111.6KB smem);
// encoder wavefront (L0(t) + L1(t-1) per phase, one barrier).
// ---------------------------------------------------------------------------

#define BSZ   512
#define HDIM  512
#define TLEN  120
#define FDIM  72
#define G4H   2048
#define INW   713
#define SH    (BSZ * HDIM)

#define NCTA  256
#define NTHR  256
#define GSTRIDE (NCTA * NTHR)

typedef __half f16;

// A block: 64 rows x 72 cols (64 data + 8 pad) fp16 = 4608 elems = 9216 B
#define BLK_A    4608
// B block: 64 N'-rows x 72 cols fp16 = 4608 elems = 9216 B
#define BLK_B    4608
#define ACHB     18432             // chunk A bytes (2 blocks) = chunk B bytes
#define CHUNKB   36864             // full chunk (A + B)
#define NSTAGE   3
#define NCHUNK   8
#define DSMEM_BYTES (NSTAGE * CHUNKB + 1024)     // 111616

#define A_T_STRIDE (64 * BLK_A)    // 8 mtiles x 8 kchunks per timestep

// ------------------------- scratch (device globals) ------------------------
__device__ f16   g_encA[(size_t)TLEN * A_T_STRIDE];   // encoder input tiles
__device__ f16   g_wB[(size_t)4 * 32 * 16 * BLK_B];   // weight tiles
__device__ f16   g_hA[2][2][A_T_STRIDE];              // h tiles [layer][parity]
__device__ f16   g_xA[A_T_STRIDE];                    // decoder embedded input
__device__ float g_hf[SH];                            // fp32 h1 for out proj
__device__ float g_c[2][SH];
__device__ float g_cpart[SH];
__device__ float g_bperm[4][G4H];
__device__ unsigned g_bar_cnt = 0;
__device__ unsigned g_bar_gen = 0;

// ------------------------------- grid barrier ------------------------------
__device__ __forceinline__ void gridbar() {
    __syncthreads();
    if (threadIdx.x == 0) {
        unsigned gen = *((volatile unsigned*)&g_bar_gen);
        __threadfence();
        if (atomicAdd(&g_bar_cnt, 1u) == NCTA - 1) {
            g_bar_cnt = 0;
            __threadfence();
            atomicExch(&g_bar_gen, gen + 1);
        } else {
            while (*((volatile unsigned*)&g_bar_gen) == gen) { }
        }
    }
    __syncthreads();
    __threadfence();
}

// ------------------------------ PTX helpers --------------------------------
__device__ __forceinline__ uint32_t smem_u32(const void* p) {
    uint32_t a;
    asm("{ .reg .u64 t; cvta.to.shared.u64 t, %1; cvt.u32.u64 %0, t; }"
        : "=r"(a) : "l"(p));
    return a;
}

__device__ __forceinline__ void ldsm_x4(uint32_t addr, uint32_t* r) {
    asm volatile("ldmatrix.sync.aligned.m8n8.x4.shared.b16 {%0,%1,%2,%3}, [%4];"
        : "=r"(r[0]), "=r"(r[1]), "=r"(r[2]), "=r"(r[3]) : "r"(addr));
}
__device__ __forceinline__ void ldsm_x2(uint32_t addr, uint32_t* r) {
    asm volatile("ldmatrix.sync.aligned.m8n8.x2.shared.b16 {%0,%1}, [%2];"
        : "=r"(r[0]), "=r"(r[1]) : "r"(addr));
}
__device__ __forceinline__ void mma16816(float* c, const uint32_t* a,
                                         const uint32_t* b) {
    asm volatile(
        "mma.sync.aligned.m16n8k16.row.col.f32.f16.f16.f32 "
        "{%0,%1,%2,%3}, {%4,%5,%6,%7}, {%8,%9}, {%0,%1,%2,%3};"
        : "+f"(c[0]), "+f"(c[1]), "+f"(c[2]), "+f"(c[3])
        : "r"(a[0]), "r"(a[1]), "r"(a[2]), "r"(a[3]), "r"(b[0]), "r"(b[1]));
}

__device__ __forceinline__ void cp16(uint32_t sdst, const void* gsrc) {
    asm volatile("cp.async.cg.shared.global [%0], [%1], 16;"
                 :: "r"(sdst), "l"(gsrc) : "memory");
}
#define CP_COMMIT() asm volatile("cp.async.commit_group;" ::: "memory")
#define CP_WAIT(n)  asm volatile("cp.async.wait_group %0;" :: "n"(n) : "memory")

// ------------------------------ math helpers -------------------------------
__device__ __forceinline__ float sigm(float x) { return 1.f / (1.f + __expf(-x)); }
__device__ __forceinline__ float tanh_f(float x) { return 2.f * sigm(2.f * x) - 1.f; }

// ---------------------------------------------------------------------------
// One LSTM cell: 64x64 tile of gates = [X|H](64x1024) @ W^T, tensor cores.
// 8 warps: wm = wid>>2 (32-row half), wn = wid&3 (16-col quarter).
// 8 chunks of 128 K-cols; 3-stage cp.async ring; one sync per chunk.
// ---------------------------------------------------------------------------
__device__ void cell_tc(const f16* __restrict__ Xt,    // + bm*8*BLK_A applied
                        const f16* __restrict__ Ht,    // + bm*8*BLK_A applied
                        const f16* __restrict__ Bt,    // 16 blocks of BLK_B
                        const float* __restrict__ bvec,// permuted bias (64)
                        float* __restrict__ Cst,
                        f16* __restrict__ HoT,         // h output tile array
                        float* __restrict__ hf,
                        uint32_t sbu, int bm, int nt)
{
    const int tid  = threadIdx.x;
    const int wid  = tid >> 5;
    const int lane = tid & 31;
    const int wm   = wid >> 2;        // 0..1  (32-row half)
    const int wn   = wid & 3;         // 0..3  (16-col quarter)

    float acc[2][2][4];
#pragma unroll
    for (int i = 0; i < 2; i++)
#pragma unroll
        for (int j = 0; j < 2; j++)
#pragma unroll
            for (int q = 0; q < 4; q++) acc[i][j][q] = 0.f;

    // per-thread ldmatrix address components (byte offsets within a block)
    const int aoff = (lane & 15) * 144 + (lane >> 4) * 16;
    const int boff = (lane & 7) * 144 + ((lane >> 3) & 1) * 16;

    auto issue_copy = [&](int q) {
        const f16* a = (q < 4) ? (Xt + (size_t)q * 2 * BLK_A)
                               : (Ht + (size_t)(q - 4) * 2 * BLK_A);
        const f16* w = Bt + (size_t)q * 2 * BLK_B;
        uint32_t dst = sbu + (uint32_t)(q % NSTAGE) * CHUNKB;
        const char* ag = (const char*)a;
        const char* wg = (const char*)w;
        for (int off = tid * 16; off < ACHB; off += NTHR * 16)
            cp16(dst + off, ag + off);
        uint32_t db = dst + ACHB;
        for (int off = tid * 16; off < ACHB; off += NTHR * 16)
            cp16(db + off, wg + off);
        CP_COMMIT();
    };

    issue_copy(0);
    issue_copy(1);
#pragma unroll 1
    for (int q = 0; q < NCHUNK; q++) {
        CP_WAIT(1);              // own groups: chunk q landed (q+1 may fly)
        __syncthreads();         // publish copies of q; all warps done q-1
        if (q < NCHUNK - 2) issue_copy(q + 2);   // reuses buffer of q-1
        else                CP_COMMIT();         // uniform group numbering

        uint32_t base = sbu + (uint32_t)(q % NSTAGE) * CHUNKB;

#pragma unroll
        for (int ks = 0; ks < 8; ks++) {
            uint32_t sb2 = (uint32_t)(ks >> 2) * 9216;
            uint32_t kb  = (uint32_t)(ks & 3) * 32;
            uint32_t aH = base + sb2 + aoff + wm * 32 * 144 + kb;
            uint32_t bH = base + ACHB + sb2 + boff + wn * 16 * 144 + kb;
            uint32_t ah[2][4], bh[2][2];
            ldsm_x4(aH, ah[0]);
            ldsm_x4(aH + 16 * 144, ah[1]);
#pragma unroll
            for (int ni = 0; ni < 2; ni++)
                ldsm_x2(bH + ni * 8 * 144, bh[ni]);
#pragma unroll
            for (int ni = 0; ni < 2; ni++) {
                mma16816(acc[0][ni], ah[0], bh[ni]);
                mma16816(acc[1][ni], ah[1], bh[ni]);
            }
        }
    }

    // ---- fused LSTM pointwise epilogue ----
    // col pair (2t,2t+1): even t holds gates (i,f), odd t holds (g,o).
    // shfl_xor(1) completes the quad; even lane -> row g, odd lane -> row g+8.
    const int g = lane >> 2, t = lane & 3;
    const int rbase = bm * 64 + wm * 32;
#pragma unroll
    for (int mi = 0; mi < 2; mi++) {
#pragma unroll
        for (int ni = 0; ni < 2; ni++) {
            float c0 = acc[mi][ni][0], c1 = acc[mi][ni][1];
            float c2 = acc[mi][ni][2], c3 = acc[mi][ni][3];
            float v0 = __shfl_xor_sync(0xffffffffu, c0, 1);
            float v1 = __shfl_xor_sync(0xffffffffu, c1, 1);
            float v2 = __shfl_xor_sync(0xffffffffu, c2, 1);
            float v3 = __shfl_xor_sync(0xffffffffu, c3, 1);
            int jl = wn * 4 + ni * 2 + (t >> 1);      // CTA-local j (0..15)
            int jg = nt * 16 + jl;                    // global j
            const float* bb = bvec + 4 * jl;
            float gi, gf, gg, go;
            int row;
            if (t & 1) { gi = v2; gf = v3; gg = c2; go = c3;
                         row = rbase + mi * 16 + g + 8; }
            else       { gi = c0; gf = c1; gg = v0; go = v1;
                         row = rbase + mi * 16 + g; }
            gi += bb[0]; gf += bb[1]; gg += bb[2]; go += bb[3];
            int cidx = row * HDIM + jg;
            float cn = sigm(gf) * Cst[cidx] + sigm(gi) * tanh_f(gg);
            Cst[cidx] = cn;
            float hn = sigm(go) * tanh_f(cn);
            if (hf) hf[cidx] = hn;
            f16* blk = HoT + (size_t)((row >> 6) * 8 + (jg >> 6)) * BLK_A;
            blk[(row & 63) * 72 + (jg & 63)] = __float2half(hn);
        }
    }
}

// ------------------------------ persistent kernel --------------------------
__global__ void __launch_bounds__(NTHR, 2) motion_persistent(
    const float* __restrict__ label,
    const float* __restrict__ ce,
    const float* __restrict__ traj,
    const float* __restrict__ enc_emb_W,
    const float* __restrict__ enc_emb_b,
    const float* __restrict__ prelu_a,
    const float* __restrict__ emb_W,
    const float* __restrict__ emb_b,
    const float* __restrict__ out_W,
    const float* __restrict__ out_b,
    const float* __restrict__ enc_Wih,
    const float* __restrict__ enc_Whh,
    const float* __restrict__ enc_bih,
    const float* __restrict__ enc_bhh,
    const float* __restrict__ dec_Wih,
    const float* __restrict__ dec_Whh,
    const float* __restrict__ dec_bih,
    const float* __restrict__ dec_bhh,
    float* __restrict__ out)
{
    extern __shared__ char dsm[];
    const int tid = threadIdx.x;
    const int gtid = blockIdx.x * NTHR + tid;
    const int bm = blockIdx.x & 7;         // 8 M-tiles (64 batch rows each)
    const int nt = blockIdx.x >> 3;        // 32 N-tiles (64 gate cols each)
    const float pa = prelu_a[0];
    const size_t WL = (size_t)G4H * HDIM;

    uint32_t du = smem_u32(dsm);
    uint32_t sbu = (du + 1023) & ~1023u;

    // ------------------------------- prep ---------------------------------
    for (int i = gtid; i < 2 * A_T_STRIDE; i += GSTRIDE)   // both layers/parities
        ((uint32_t*)g_hA)[i] = 0u;
    for (int i = gtid; i < 2 * SH; i += GSTRIDE) ((float*)g_c)[i] = 0.f;

    for (int i = gtid; i < 4 * G4H; i += GSTRIDE) {
        int l = i >> 11, np = i & (G4H - 1);
        int orig = (np & 3) * 512 + (np >> 2);
        float v;
        if (l == 0)      v = enc_bih[orig] + enc_bhh[orig];
        else if (l == 1) v = enc_bih[G4H + orig] + enc_bhh[G4H + orig];
        else if (l == 2) v = dec_bih[orig] + dec_bhh[orig];
        else             v = dec_bih[G4H + orig] + dec_bhh[G4H + orig];
        ((float*)g_bperm)[i] = v;
    }

    // encoder inputs -> fp16 tiles
    for (int i = gtid; i < TLEN * SH; i += GSTRIDE) {
        int tt = i >> 18, rem = i & (SH - 1);
        int b = rem >> 9, h = rem & 511;
        const float* tr = traj + ((size_t)b * TLEN + tt) * 3;
        float v = fmaf(enc_emb_W[h * 3 + 0], tr[0],
                   fmaf(enc_emb_W[h * 3 + 1], tr[1],
                    fmaf(enc_emb_W[h * 3 + 2], tr[2], enc_emb_b[h])));
        v = (v >= 0.f) ? v : pa * v;
        f16* blk = g_encA + (size_t)tt * A_T_STRIDE
                 + (size_t)((b >> 6) * 8 + (h >> 6)) * BLK_A;
        blk[(b & 63) * 72 + (h & 63)] = __float2half(v);
    }

    // weights -> permuted fp16 tiles (4 layers x 32 nt x 16 q x 4608 elems)
    for (int i = gtid; i < 4 * 32 * 16 * BLK_B; i += GSTRIDE) {
        int e  = i % BLK_B;                 // elem in 64x72 block
        int r1 = i / BLK_B;
        int q  = r1 & 15;
        int r2 = r1 >> 4;
        int ntb = r2 & 31;
        int l  = r2 >> 5;
        int row = e / 72, kc = e % 72;
        if (kc >= 64) continue;
        int np = 64 * ntb + row;
        int orig = (np & 3) * 512 + (np >> 2);
        const float* ih, * hh;
        if (l == 0)      { ih = enc_Wih;      hh = enc_Whh; }
        else if (l == 1) { ih = enc_Wih + WL; hh = enc_Whh + WL; }
        else if (l == 2) { ih = dec_Wih;      hh = dec_Whh; }
        else             { ih = dec_Wih + WL; hh = dec_Whh + WL; }
        const float* W = (q < 8) ? ih : hh;
        float w = W[(size_t)orig * HDIM + ((q & 7) << 6) + kc];
        f16* blk = g_wB + (size_t)((l * 32 + ntb) * 16 + q) * BLK_B;
        blk[row * 72 + kc] = __float2half(w);
    }

    // cond part (time-invariant decoder embedding piece)
    for (int i = gtid; i < SH; i += GSTRIDE) {
        int b = i >> 9, h = i & 511;
        const float* w = emb_W + (size_t)h * INW + FDIM;
        const float* lb = label + b * 10;
        const float* cb = ce + b * 64;
        float acc = emb_b[h];
#pragma unroll 1
        for (int ii = 0; ii < 10; ii++) {
            float lv = lb[ii];
            const float* wr = w + ii * 64;
#pragma unroll 8
            for (int jj = 0; jj < 64; jj++)
                acc = fmaf(lv * cb[jj], wr[jj], acc);
        }
        g_cpart[i] = acc;
    }
    gridbar();

    const size_t bmoff = (size_t)bm * 8 * BLK_A;
    const f16* Bt0 = g_wB + (size_t)((0 * 32 + nt) * 16) * BLK_B;
    const f16* Bt1 = g_wB + (size_t)((1 * 32 + nt) * 16) * BLK_B;
    const f16* Bt2 = g_wB + (size_t)((2 * 32 + nt) * 16) * BLK_B;
    const f16* Bt3 = g_wB + (size_t)((3 * 32 + nt) * 16) * BLK_B;

    // ------------------- encoder (wavefront: L0(k) + L1(k-1)) --------------
    for (int k = 0; k <= TLEN; k++) {
        if (k < TLEN) {
            int p = k & 1;
            cell_tc(g_encA + (size_t)k * A_T_STRIDE + bmoff,
                    g_hA[0][p] + bmoff, Bt0, g_bperm[0] + 64 * nt,
                    g_c[0], g_hA[0][p ^ 1], nullptr, sbu, bm, nt);
        }
        if (k > 0) {
            int t1 = k - 1;
            int p1 = t1 & 1;
            cell_tc(g_hA[0][p1 ^ 1] + bmoff,
                    g_hA[1][p1] + bmoff, Bt1, g_bperm[1] + 64 * nt,
                    g_c[1], g_hA[1][p1 ^ 1], nullptr, sbu, bm, nt);
        }
        gridbar();
    }

    // ------------------------------ decoder -------------------------------
    for (int t = 0; t < TLEN; t++) {
        int p = t & 1;
        float ts = (float)(t + 1) * (1.0f / (float)TLEN);
        for (int i = gtid; i < SH; i += GSTRIDE) {
            int b = i >> 9, h = i & 511;
            const float* w = emb_W + (size_t)h * INW;
            float acc = g_cpart[i] + ts * w[712];
            if (t > 0) {
                const float* dn = out + ((size_t)b * TLEN + (t - 1)) * FDIM;
#pragma unroll
                for (int f = 0; f < FDIM; f++) acc = fmaf(dn[f], w[f], acc);
            }
            acc = (acc >= 0.f) ? acc : pa * acc;
            f16* blk = g_xA + (size_t)((b >> 6) * 8 + (h >> 6)) * BLK_A;
            blk[(b & 63) * 72 + (h & 63)] = __float2half(acc);
        }
        gridbar();

        cell_tc(g_xA + bmoff,
                g_hA[0][p] + bmoff, Bt2, g_bperm[2] + 64 * nt,
                g_c[0], g_hA[0][p ^ 1], nullptr, sbu, bm, nt);
        gridbar();
        cell_tc(g_hA[0][p ^ 1] + bmoff,
                g_hA[1][p] + bmoff, Bt3, g_bperm[3] + 64 * nt,
                g_c[1], g_hA[1][p ^ 1], g_hf, sbu, bm, nt);
        gridbar();

        // output projection: out[b,t,f] = h1[b] @ out_W[f] + out_b[f]
        for (int i = gtid; i < BSZ * FDIM; i += GSTRIDE) {
            int b = i / FDIM, f = i - b * FDIM;
            const float4* hv = (const float4*)(g_hf + (size_t)b * HDIM);
            const float4* wv = (const float4*)(out_W + (size_t)f * HDIM);
            float acc = 0.f;
#pragma unroll 8
            for (int k = 0; k < HDIM / 4; k++) {
                float4 a = hv[k], w = wv[k];
                acc = fmaf(a.x, w.x, acc);
                acc = fmaf(a.y, w.y, acc);
                acc = fmaf(a.z, w.z, acc);
                acc = fmaf(a.w, w.w, acc);
            }
            out[((size_t)b * TLEN + t) * FDIM + f] = acc + out_b[f];
        }
        gridbar();
    }
}

// ------------------------------- host driver -------------------------------
extern "C" void kernel_launch(void* const* d_in, const int* in_sizes, int n_in,
                              void* d_out, int out_size) {
    const float* label      = (const float*)d_in[1];
    const float* ce         = (const float*)d_in[2];
    const float* traj       = (const float*)d_in[3];
    const float* enc_emb_W  = (const float*)d_in[4];
    const float* enc_emb_b  = (const float*)d_in[5];
    const float* prelu_a    = (const float*)d_in[6];
    const float* emb_W      = (const float*)d_in[7];
    const float* emb_b      = (const float*)d_in[8];
    const float* out_W      = (const float*)d_in[9];
    const float* out_b      = (const float*)d_in[10];
    const float* enc_Wih    = (const float*)d_in[11];
    const float* enc_Whh    = (const float*)d_in[12];
    const float* enc_bih    = (const float*)d_in[13];
    const float* enc_bhh    = (const float*)d_in[14];
    const float* dec_Wih    = (const float*)d_in[15];
    const float* dec_Whh    = (const float*)d_in[16];
    const float* dec_bih    = (const float*)d_in[17];
    const float* dec_bhh    = (const float*)d_in[18];

    cudaFuncSetAttribute(motion_persistent,
                         cudaFuncAttributeMaxDynamicSharedMemorySize, DSMEM_BYTES);
    motion_persistent<<<NCTA, NTHR, DSMEM_BYTES>>>(
        label, ce, traj, enc_emb_W, enc_emb_b, prelu_a, emb_W, emb_b,
        out_W, out_b, enc_Wih, enc_Whh, enc_bih, enc_bhh,
        dec_Wih, dec_Whh, dec_bih, dec_bhh, (float*)d_out);
}

// round 17
// speedup vs baseline: 1.6072x; 1.6072x over previous
#include <cuda_runtime.h>
#include <cuda_fp16.h>
#include <cstdint>

// ---------------------------------------------------------------------------
// MotionGenerator seq2seq LSTM (B=512,H=512,L=2,T=120) — persistent kernel.
// Tensor-core cells via mma.sync fp16 (plain sm_103 target).
// R17: R15 base (256 CTAs = 2/SM, tile 64x64, 18.4KB chunks) +
//   (a) 4-stage cp.async ring, CP_WAIT(2) -> copy window ~3 chunks
//   (b) encoder wavefront: L0(k) + L1(k-1) per phase, single barrier
// fp32 accumulators + fp32 cell state. rel_err target: 3.86e-4 (unchanged).
// ---------------------------------------------------------------------------

#define BSZ   512
#define HDIM  512
#define TLEN  120
#define FDIM  72
#define G4H   2048
#define INW   713
#define SH    (BSZ * HDIM)

#define NCTA  256
#define NTHR  256
#define GSTRIDE (NCTA * NTHR)

typedef __half f16;

// A block: 64 rows x 72 cols (64 data + 8 pad) fp16 = 4608 elems = 9216 B
#define BLK_A    4608
// B block: 64 N'-rows x 72 cols fp16 = 4608 elems = 9216 B
#define BLK_B    4608
#define ABYTES   (BLK_A * 2)       // 9216
#define BBYTES   (BLK_B * 2)       // 9216
#define BUFBYTES (ABYTES + BBYTES) // 18432
#define NSTAGE   4
#define NCHUNK   16
#define DSMEM_BYTES (NSTAGE * BUFBYTES + 1024)   // 74752/CTA -> 149.5KB/SM

#define A_T_STRIDE (64 * BLK_A)    // 8 mtiles x 8 kchunks per timestep

// ------------------------- scratch (device globals) ------------------------
__device__ f16   g_encA[(size_t)TLEN * A_T_STRIDE];   // encoder input tiles
__device__ f16   g_wB[(size_t)4 * 32 * 16 * BLK_B];   // weight tiles
__device__ f16   g_hA[2][2][A_T_STRIDE];              // h tiles [layer][parity]
__device__ f16   g_xA[A_T_STRIDE];                    // decoder embedded input
__device__ float g_hf[SH];                            // fp32 h1 for out proj
__device__ float g_c[2][SH];
__device__ float g_cpart[SH];
__device__ float g_bperm[4][G4H];
__device__ unsigned g_bar_cnt = 0;
__device__ unsigned g_bar_gen = 0;

// ------------------------------- grid barrier ------------------------------
__device__ __forceinline__ void gridbar() {
    __syncthreads();
    if (threadIdx.x == 0) {
        unsigned gen = *((volatile unsigned*)&g_bar_gen);
        __threadfence();
        if (atomicAdd(&g_bar_cnt, 1u) == NCTA - 1) {
            g_bar_cnt = 0;
            __threadfence();
            atomicExch(&g_bar_gen, gen + 1);
        } else {
            while (*((volatile unsigned*)&g_bar_gen) == gen) { }
        }
    }
    __syncthreads();
    __threadfence();
}

// ------------------------------ PTX helpers --------------------------------
__device__ __forceinline__ uint32_t smem_u32(const void* p) {
    uint32_t a;
    asm("{ .reg .u64 t; cvta.to.shared.u64 t, %1; cvt.u32.u64 %0, t; }"
        : "=r"(a) : "l"(p));
    return a;
}

__device__ __forceinline__ void ldsm_x4(uint32_t addr, uint32_t* r) {
    asm volatile("ldmatrix.sync.aligned.m8n8.x4.shared.b16 {%0,%1,%2,%3}, [%4];"
        : "=r"(r[0]), "=r"(r[1]), "=r"(r[2]), "=r"(r[3]) : "r"(addr));
}
__device__ __forceinline__ void ldsm_x2(uint32_t addr, uint32_t* r) {
    asm volatile("ldmatrix.sync.aligned.m8n8.x2.shared.b16 {%0,%1}, [%2];"
        : "=r"(r[0]), "=r"(r[1]) : "r"(addr));
}
__device__ __forceinline__ void mma16816(float* c, const uint32_t* a,
                                         const uint32_t* b) {
    asm volatile(
        "mma.sync.aligned.m16n8k16.row.col.f32.f16.f16.f32 "
        "{%0,%1,%2,%3}, {%4,%5,%6,%7}, {%8,%9}, {%0,%1,%2,%3};"
        : "+f"(c[0]), "+f"(c[1]), "+f"(c[2]), "+f"(c[3])
        : "r"(a[0]), "r"(a[1]), "r"(a[2]), "r"(a[3]), "r"(b[0]), "r"(b[1]));
}

__device__ __forceinline__ void cp16(uint32_t sdst, const void* gsrc) {
    asm volatile("cp.async.cg.shared.global [%0], [%1], 16;"
                 :: "r"(sdst), "l"(gsrc) : "memory");
}
#define CP_COMMIT() asm volatile("cp.async.commit_group;" ::: "memory")
#define CP_WAIT(n)  asm volatile("cp.async.wait_group %0;" :: "n"(n) : "memory")

// ------------------------------ math helpers -------------------------------
__device__ __forceinline__ float sigm(float x) { return 1.f / (1.f + __expf(-x)); }
__device__ __forceinline__ float tanh_f(float x) { return 2.f * sigm(2.f * x) - 1.f; }

// ---------------------------------------------------------------------------
// One LSTM cell: 64x64 tile of gates = [X|H](64x1024) @ W^T, tensor cores.
// 8 warps: wm = wid>>2 (32-row half), wn = wid&3 (16-col quarter).
// 16 chunks of 64 K-cols; 4-stage cp.async ring (copy window ~3 chunks).
// ---------------------------------------------------------------------------
__device__ void cell_tc(const f16* __restrict__ Xt,    // + bm*8*BLK_A applied
                        const f16* __restrict__ Ht,    // + bm*8*BLK_A applied
                        const f16* __restrict__ Bt,    // 16 chunks of BLK_B
                        const float* __restrict__ bvec,// permuted bias (64)
                        float* __restrict__ Cst,
                        f16* __restrict__ HoT,         // h output tile array
                        float* __restrict__ hf,
                        uint32_t sbu, int bm, int nt)
{
    const int tid  = threadIdx.x;
    const int wid  = tid >> 5;
    const int lane = tid & 31;
    const int wm   = wid >> 2;        // 0..1  (32-row half)
    const int wn   = wid & 3;         // 0..3  (16-col quarter)

    float acc[2][2][4];
#pragma unroll
    for (int i = 0; i < 2; i++)
#pragma unroll
        for (int j = 0; j < 2; j++)
#pragma unroll
            for (int q = 0; q < 4; q++) acc[i][j][q] = 0.f;

    // per-thread ldmatrix address components (byte offsets within a block)
    const int aoff = (lane & 15) * 144 + (lane >> 4) * 16;
    const int boff = (lane & 7) * 144 + ((lane >> 3) & 1) * 16;

    auto issue_copy = [&](int q) {
        const f16* a = (q < 8) ? (Xt + (size_t)q * BLK_A)
                               : (Ht + (size_t)(q - 8) * BLK_A);
        const f16* w = Bt + (size_t)q * BLK_B;
        uint32_t dst = sbu + (uint32_t)(q % NSTAGE) * BUFBYTES;
        const char* ag = (const char*)a;
        const char* wg = (const char*)w;
        for (int off = tid * 16; off < ABYTES; off += NTHR * 16)
            cp16(dst + off, ag + off);
        uint32_t db = dst + ABYTES;
        for (int off = tid * 16; off < BBYTES; off += NTHR * 16)
            cp16(db + off, wg + off);
        CP_COMMIT();
    };

    issue_copy(0);
    issue_copy(1);
    issue_copy(2);
#pragma unroll 1
    for (int q = 0; q < NCHUNK; q++) {
        CP_WAIT(2);              // chunk q landed; q+1, q+2 may still fly
        __syncthreads();         // publish copies of q; all warps done q-1
        if (q < NCHUNK - 3) issue_copy(q + 3);   // reuses buffer of q-1
        else                CP_COMMIT();         // uniform group numbering

        uint32_t base = sbu + (uint32_t)(q % NSTAGE) * BUFBYTES;
        uint32_t aH = base + aoff + wm * 32 * 144;
        uint32_t bH = base + ABYTES + boff + wn * 16 * 144;

#pragma unroll
        for (int ks = 0; ks < 4; ks++) {
            uint32_t kb = ks * 32;                    // k16 step -> 32 bytes
            uint32_t ah[2][4], bh[2][2];
            ldsm_x4(aH + kb, ah[0]);
            ldsm_x4(aH + 16 * 144 + kb, ah[1]);
#pragma unroll
            for (int ni = 0; ni < 2; ni++)
                ldsm_x2(bH + ni * 8 * 144 + kb, bh[ni]);
#pragma unroll
            for (int ni = 0; ni < 2; ni++) {
                mma16816(acc[0][ni], ah[0], bh[ni]);
                mma16816(acc[1][ni], ah[1], bh[ni]);
            }
        }
    }

    // ---- fused LSTM pointwise epilogue ----
    // col pair (2t,2t+1): even t holds gates (i,f), odd t holds (g,o).
    // shfl_xor(1) completes the quad; even lane -> row g, odd lane -> row g+8.
    const int g = lane >> 2, t = lane & 3;
    const int rbase = bm * 64 + wm * 32;
#pragma unroll
    for (int mi = 0; mi < 2; mi++) {
#pragma unroll
        for (int ni = 0; ni < 2; ni++) {
            float c0 = acc[mi][ni][0], c1 = acc[mi][ni][1];
            float c2 = acc[mi][ni][2], c3 = acc[mi][ni][3];
            float v0 = __shfl_xor_sync(0xffffffffu, c0, 1);
            float v1 = __shfl_xor_sync(0xffffffffu, c1, 1);
            float v2 = __shfl_xor_sync(0xffffffffu, c2, 1);
            float v3 = __shfl_xor_sync(0xffffffffu, c3, 1);
            int jl = wn * 4 + ni * 2 + (t >> 1);      // CTA-local j (0..15)
            int jg = nt * 16 + jl;                    // global j
            const float* bb = bvec + 4 * jl;
            float gi, gf, gg, go;
            int row;
            if (t & 1) { gi = v2; gf = v3; gg = c2; go = c3;
                         row = rbase + mi * 16 + g + 8; }
            else       { gi = c0; gf = c1; gg = v0; go = v1;
                         row = rbase + mi * 16 + g; }
            gi += bb[0]; gf += bb[1]; gg += bb[2]; go += bb[3];
            int cidx = row * HDIM + jg;
            float cn = sigm(gf) * Cst[cidx] + sigm(gi) * tanh_f(gg);
            Cst[cidx] = cn;
            float hn = sigm(go) * tanh_f(cn);
            if (hf) hf[cidx] = hn;
            f16* blk = HoT + (size_t)((row >> 6) * 8 + (jg >> 6)) * BLK_A;
            blk[(row & 63) * 72 + (jg & 63)] = __float2half(hn);
        }
    }
}

// ------------------------------ persistent kernel --------------------------
__global__ void __launch_bounds__(NTHR, 2) motion_persistent(
    const float* __restrict__ label,
    const float* __restrict__ ce,
    const float* __restrict__ traj,
    const float* __restrict__ enc_emb_W,
    const float* __restrict__ enc_emb_b,
    const float* __restrict__ prelu_a,
    const float* __restrict__ emb_W,
    const float* __restrict__ emb_b,
    const float* __restrict__ out_W,
    const float* __restrict__ out_b,
    const float* __restrict__ enc_Wih,
    const float* __restrict__ enc_Whh,
    const float* __restrict__ enc_bih,
    const float* __restrict__ enc_bhh,
    const float* __restrict__ dec_Wih,
    const float* __restrict__ dec_Whh,
    const float* __restrict__ dec_bih,
    const float* __restrict__ dec_bhh,
    float* __restrict__ out)
{
    extern __shared__ char dsm[];
    const int tid = threadIdx.x;
    const int gtid = blockIdx.x * NTHR + tid;
    const int bm = blockIdx.x & 7;         // 8 M-tiles (64 batch rows each)
    const int nt = blockIdx.x >> 3;        // 32 N-tiles (64 gate cols each)
    const float pa = prelu_a[0];
    const size_t WL = (size_t)G4H * HDIM;

    uint32_t du = smem_u32(dsm);
    uint32_t sbu = (du + 1023) & ~1023u;

    // ------------------------------- prep ---------------------------------
    for (int i = gtid; i < 2 * A_T_STRIDE; i += GSTRIDE)   // both layers/parities
        ((uint32_t*)g_hA)[i] = 0u;
    for (int i = gtid; i < 2 * SH; i += GSTRIDE) ((float*)g_c)[i] = 0.f;

    for (int i = gtid; i < 4 * G4H; i += GSTRIDE) {
        int l = i >> 11, np = i & (G4H - 1);
        int orig = (np & 3) * 512 + (np >> 2);
        float v;
        if (l == 0)      v = enc_bih[orig] + enc_bhh[orig];
        else if (l == 1) v = enc_bih[G4H + orig] + enc_bhh[G4H + orig];
        else if (l == 2) v = dec_bih[orig] + dec_bhh[orig];
        else             v = dec_bih[G4H + orig] + dec_bhh[G4H + orig];
        ((float*)g_bperm)[i] = v;
    }

    // encoder inputs -> fp16 tiles
    for (int i = gtid; i < TLEN * SH; i += GSTRIDE) {
        int tt = i >> 18, rem = i & (SH - 1);
        int b = rem >> 9, h = rem & 511;
        const float* tr = traj + ((size_t)b * TLEN + tt) * 3;
        float v = fmaf(enc_emb_W[h * 3 + 0], tr[0],
                   fmaf(enc_emb_W[h * 3 + 1], tr[1],
                    fmaf(enc_emb_W[h * 3 + 2], tr[2], enc_emb_b[h])));
        v = (v >= 0.f) ? v : pa * v;
        f16* blk = g_encA + (size_t)tt * A_T_STRIDE
                 + (size_t)((b >> 6) * 8 + (h >> 6)) * BLK_A;
        blk[(b & 63) * 72 + (h & 63)] = __float2half(v);
    }

    // weights -> permuted fp16 tiles (4 layers x 32 nt x 16 q x 4608 elems)
    for (int i = gtid; i < 4 * 32 * 16 * BLK_B; i += GSTRIDE) {
        int e  = i % BLK_B;                 // elem in 64x72 block
        int r1 = i / BLK_B;
        int q  = r1 & 15;
        int r2 = r1 >> 4;
        int ntb = r2 & 31;
        int l  = r2 >> 5;
        int row = e / 72, kc = e % 72;
        if (kc >= 64) continue;
        int np = 64 * ntb + row;
        int orig = (np & 3) * 512 + (np >> 2);
        const float* ih, * hh;
        if (l == 0)      { ih = enc_Wih;      hh = enc_Whh; }
        else if (l == 1) { ih = enc_Wih + WL; hh = enc_Whh + WL; }
        else if (l == 2) { ih = dec_Wih;      hh = dec_Whh; }
        else             { ih = dec_Wih + WL; hh = dec_Whh + WL; }
        const float* W = (q < 8) ? ih : hh;
        float w = W[(size_t)orig * HDIM + ((q & 7) << 6) + kc];
        f16* blk = g_wB + (size_t)((l * 32 + ntb) * 16 + q) * BLK_B;
        blk[row * 72 + kc] = __float2half(w);
    }

    // cond part (time-invariant decoder embedding piece)
    for (int i = gtid; i < SH; i += GSTRIDE) {
        int b = i >> 9, h = i & 511;
        const float* w = emb_W + (size_t)h * INW + FDIM;
        const float* lb = label + b * 10;
        const float* cb = ce + b * 64;
        float acc = emb_b[h];
#pragma unroll 1
        for (int ii = 0; ii < 10; ii++) {
            float lv = lb[ii];
            const float* wr = w + ii * 64;
#pragma unroll 8
            for (int jj = 0; jj < 64; jj++)
                acc = fmaf(lv * cb[jj], wr[jj], acc);
        }
        g_cpart[i] = acc;
    }
    gridbar();

    const size_t bmoff = (size_t)bm * 8 * BLK_A;
    const f16* Bt0 = g_wB + (size_t)((0 * 32 + nt) * 16) * BLK_B;
    const f16* Bt1 = g_wB + (size_t)((1 * 32 + nt) * 16) * BLK_B;
    const f16* Bt2 = g_wB + (size_t)((2 * 32 + nt) * 16) * BLK_B;
    const f16* Bt3 = g_wB + (size_t)((3 * 32 + nt) * 16) * BLK_B;

    // ------------------- encoder (wavefront: L0(k) + L1(k-1)) --------------
    for (int k = 0; k <= TLEN; k++) {
        if (k < TLEN) {
            int p = k & 1;
            cell_tc(g_encA + (size_t)k * A_T_STRIDE + bmoff,
                    g_hA[0][p] + bmoff, Bt0, g_bperm[0] + 64 * nt,
                    g_c[0], g_hA[0][p ^ 1], nullptr, sbu, bm, nt);
        }
        if (k > 0) {
            int t1 = k - 1;
            int p1 = t1 & 1;
            cell_tc(g_hA[0][p1 ^ 1] + bmoff,
                    g_hA[1][p1] + bmoff, Bt1, g_bperm[1] + 64 * nt,
                    g_c[1], g_hA[1][p1 ^ 1], nullptr, sbu, bm, nt);
        }
        gridbar();
    }

    // ------------------------------ decoder -------------------------------
    for (int t = 0; t < TLEN; t++) {
        int p = t & 1;
        float ts = (float)(t + 1) * (1.0f / (float)TLEN);
        for (int i = gtid; i < SH; i += GSTRIDE) {
            int b = i >> 9, h = i & 511;
            const float* w = emb_W + (size_t)h * INW;
            float acc = g_cpart[i] + ts * w[712];
            if (t > 0) {
                const float* dn = out + ((size_t)b * TLEN + (t - 1)) * FDIM;
#pragma unroll
                for (int f = 0; f < FDIM; f++) acc = fmaf(dn[f], w[f], acc);
            }
            acc = (acc >= 0.f) ? acc : pa * acc;
            f16* blk = g_xA + (size_t)((b >> 6) * 8 + (h >> 6)) * BLK_A;
            blk[(b & 63) * 72 + (h & 63)] = __float2half(acc);
        }
        gridbar();

        cell_tc(g_xA + bmoff,
                g_hA[0][p] + bmoff, Bt2, g_bperm[2] + 64 * nt,
                g_c[0], g_hA[0][p ^ 1], nullptr, sbu, bm, nt);
        gridbar();
        cell_tc(g_hA[0][p ^ 1] + bmoff,
                g_hA[1][p] + bmoff, Bt3, g_bperm[3] + 64 * nt,
                g_c[1], g_hA[1][p ^ 1], g_hf, sbu, bm, nt);
        gridbar();

        // output projection: out[b,t,f] = h1[b] @ out_W[f] + out_b[f]
        for (int i = gtid; i < BSZ * FDIM; i += GSTRIDE) {
            int b = i / FDIM, f = i - b * FDIM;
            const float4* hv = (const float4*)(g_hf + (size_t)b * HDIM);
            const float4* wv = (const float4*)(out_W + (size_t)f * HDIM);
            float acc = 0.f;
#pragma unroll 8
            for (int k = 0; k < HDIM / 4; k++) {
                float4 a = hv[k], w = wv[k];
                acc = fmaf(a.x, w.x, acc);
                acc = fmaf(a.y, w.y, acc);
                acc = fmaf(a.z, w.z, acc);
                acc = fmaf(a.w, w.w, acc);
            }
            out[((size_t)b * TLEN + t) * FDIM + f] = acc + out_b[f];
        }
        gridbar();
    }
}

// ------------------------------- host driver -------------------------------
extern "C" void kernel_launch(void* const* d_in, const int* in_sizes, int n_in,
                              void* d_out, int out_size) {
    const float* label      = (const float*)d_in[1];
    const float* ce         = (const float*)d_in[2];
    const float* traj       = (const float*)d_in[3];
    const float* enc_emb_W  = (const float*)d_in[4];
    const float* enc_emb_b  = (const float*)d_in[5];
    const float* prelu_a    = (const float*)d_in[6];
    const float* emb_W      = (const float*)d_in[7];
    const float* emb_b      = (const float*)d_in[8];
    const float* out_W      = (const float*)d_in[9];
    const float* out_b      = (const float*)d_in[10];
    const float* enc_Wih    = (const float*)d_in[11];
    const float* enc_Whh    = (const float*)d_in[12];
    const float* enc_bih    = (const float*)d_in[13];
    const float* enc_bhh    = (const float*)d_in[14];
    const float* dec_Wih    = (const float*)d_in[15];
    const float* dec_Whh    = (const float*)d_in[16];
    const float* dec_bih    = (const float*)d_in[17];
    const float* dec_bhh    = (const float*)d_in[18];

    cudaFuncSetAttribute(motion_persistent,
                         cudaFuncAttributeMaxDynamicSharedMemorySize, DSMEM_BYTES);
    motion_persistent<<<NCTA, NTHR, DSMEM_BYTES>>>(
        label, ce, traj, enc_emb_W, enc_emb_b, prelu_a, emb_W, emb_b,
        out_W, out_b, enc_Wih, enc_Whh, enc_bih, enc_bhh,
        dec_Wih, dec_Whh, dec_bih, dec_bhh, (float*)d_out);
}